// round 9
// baseline (speedup 1.0000x reference)
#include <cuda_runtime.h>
#include <cuda_fp16.h>
#include <cstdint>

#define DI __device__ __forceinline__

// ---------------- problem constants ----------------
constexpr int BATCH   = 16384;
constexpr int INF     = 512;
constexpr int OUTF    = 512;
constexpr int NG      = 8;
constexpr int KTOT    = INF * NG;    // 4096
constexpr int KC      = 128;         // K per chunk (two 128B-row planes)
constexpr int NCH     = KTOT / KC;   // 32 chunks
constexpr int MT      = 128;         // M tile per CTA
constexpr int NT      = 64;          // N tile per CTA
constexpr int THREADS = 256;
constexpr int STAGES  = 3;

constexpr int A_PLANE = 128 * 128;                // 16 KB
constexpr int B_PLANE = 64 * 128;                 // 8 KB
constexpr int A_BYTES = 2 * A_PLANE;              // 32 KB
constexpr int B_BYTES = 2 * B_PLANE;              // 16 KB
constexpr int STAGE_BYTES = A_BYTES + B_BYTES;    // 48 KB
constexpr int SMEM_DYN = STAGES * STAGE_BYTES + 1024;  // ~145 KB -> 1 CTA/SM

// fp16 W transposed to [OUTF, KTOT], K contiguous
__device__ __half g_Wt[(size_t)OUTF * KTOT];

// ---------------- PTX helpers ----------------
DI uint32_t smem_u32(const void* p) {
    uint32_t a;
    asm("{ .reg .u64 t; cvta.to.shared.u64 t, %1; cvt.u32.u64 %0, t; }" : "=r"(a) : "l"(p));
    return a;
}

// pack (lo,hi) fp32 -> f16x2 and take 2^x on both halves in one MUFU op
DI uint32_t ex2_f16x2(float lo, float hi) {
    uint32_t d;
    asm("{ .reg .b32 t; cvt.rn.f16x2.f32 t, %1, %2; ex2.approx.f16x2 %0, t; }"
        : "=r"(d) : "f"(hi), "f"(lo));
    return d;
}

DI uint32_t swz(uint32_t off) { return off ^ ((off >> 3) & 0x70u); }

DI void ldmx4(uint32_t* r, uint32_t addr) {
    asm volatile("ldmatrix.sync.aligned.m8n8.x4.shared.b16 {%0,%1,%2,%3}, [%4];"
                 : "=r"(r[0]), "=r"(r[1]), "=r"(r[2]), "=r"(r[3]) : "r"(addr));
}

DI void mma16816(float* c, const uint32_t* a, const uint32_t* b) {
    asm volatile(
        "mma.sync.aligned.m16n8k16.row.col.f32.f16.f16.f32 "
        "{%0,%1,%2,%3}, {%4,%5,%6,%7}, {%8,%9}, {%0,%1,%2,%3};"
        : "+f"(c[0]), "+f"(c[1]), "+f"(c[2]), "+f"(c[3])
        : "r"(a[0]), "r"(a[1]), "r"(a[2]), "r"(a[3]), "r"(b[0]), "r"(b[1]));
}

DI void cp_async16(uint32_t dst, const void* src) {
    asm volatile("cp.async.cg.shared.global [%0], [%1], 16;" :: "r"(dst), "l"(src) : "memory");
}
#define CP_COMMIT() asm volatile("cp.async.commit_group;" ::: "memory")
#define CP_WAIT1()  asm volatile("cp.async.wait_group 1;" ::: "memory")

// ---------------- kernel 1: W[K,N] f32 -> Wt[N,K] fp16 ----------------
__global__ void wt_kernel(const float* __restrict__ W) {
    __shared__ float tile[32][33];
    int k0 = blockIdx.x * 32, n0 = blockIdx.y * 32;
    int tx = threadIdx.x, ty = threadIdx.y;
#pragma unroll
    for (int i = 0; i < 32; i += 8)
        tile[ty + i][tx] = W[(size_t)(k0 + ty + i) * OUTF + n0 + tx];
    __syncthreads();
#pragma unroll
    for (int i = 0; i < 32; i += 8)
        g_Wt[(size_t)(n0 + ty + i) * KTOT + k0 + tx] = __float2half_rn(tile[tx][ty + i]);
}

// ---------------- kernel 2: fused basis + mma.sync GEMM ----------------
struct Ctx {
    float aco;
    float nb[8];
    const float* xthr;      // x row m, feature offset half*8
    const __half* wbase;    // Wt + Ntile*NT*KTOT
    int tid, m, half;
};

// B slice: 1 cp.async per thread per ks (only ks 0..3); 16 KB over 4 slices
DI void produce_B_slice(const Ctx& ctx, int c, uint32_t bBase, int sl) {
    int idx = ctx.tid + THREADS * sl;     // 0..1023 16B units
    int pl  = idx >> 9;                   // plane (k half)
    int rem = idx & 511;
    int n   = rem >> 3;                   // local out-feature row (0..63)
    int seg = rem & 7;
    uint32_t off = (uint32_t)(n * 128 + seg * 16);
    const void* g = (const void*)(ctx.wbase + (size_t)n * KTOT + c * KC + pl * 64 + seg * 8);
    cp_async16(bBase + pl * B_PLANE + swz(off), g);
}

// A slice: one feature (sl = 0..7) -> 8 gaussian values -> one 16B store
// thread covers k-plane = ctx.half, row m, byte offset sl*16 within the plane
DI void produce_A_slice(const Ctx& ctx, uint32_t aBase, float xf, int sl) {
    uint32_t pk[4];
#pragma unroll
    for (int q = 0; q < 4; q++) {
        float v0 = fmaf(xf, ctx.aco, ctx.nb[2 * q]);
        float v1 = fmaf(xf, ctx.aco, ctx.nb[2 * q + 1]);
        // exp(-u^2) = 2^(-(u*sqrt(log2 e))^2); both halves in one MUFU
        pk[q] = ex2_f16x2(-(v0 * v0), -(v1 * v1));
    }
    uint32_t off = (uint32_t)(ctx.m * 128 + sl * 16);
    asm volatile("st.shared.v4.b32 [%0], {%1, %2, %3, %4};"
                 :: "r"(aBase + ctx.half * A_PLANE + swz(off)),
                    "r"(pk[0]), "r"(pk[1]), "r"(pk[2]), "r"(pk[3])
                 : "memory");
}

__global__ void __launch_bounds__(THREADS, 1)
gk_kernel(const float* __restrict__ x, const float* __restrict__ grid,
          float* __restrict__ out)
{
    extern __shared__ char smem[];
    uint32_t sb = (smem_u32(smem) + 1023u) & ~1023u;

    int tid  = threadIdx.x;
    int lane = tid & 31;
    int wid  = tid >> 5;
    // n-major CTA order: consecutive bids share the same B block (L2 reuse)
    int Mtile = blockIdx.x & 127;
    int Ntile = blockIdx.x >> 7;

    Ctx ctx;
    ctx.aco = 1.75f * 1.2011224087864498f;   // (1/h)*sqrt(log2 e), h = 4/7
#pragma unroll
    for (int g = 0; g < 8; g++) ctx.nb[g] = -grid[g] * ctx.aco;
    ctx.tid   = tid;
    ctx.m     = tid >> 1;
    ctx.half  = tid & 1;
    // chunk c covers input features [c*16, c*16+16); this thread: half*8 + 0..7
    ctx.xthr  = x + (size_t)(Mtile * MT + ctx.m) * INF + ctx.half * 8;
    ctx.wbase = g_Wt + (size_t)(Ntile * NT) * KTOT;

    uint32_t aBuf[STAGES], bBuf[STAGES];
#pragma unroll
    for (int s = 0; s < STAGES; s++) {
        aBuf[s] = sb + s * STAGE_BYTES;
        bBuf[s] = aBuf[s] + A_BYTES;
    }

    // warp tiling: 8 warps = 4(M) x 2(N); warp tile 32x32
    int wm = wid >> 1;
    int wn = wid & 1;

    uint32_t aOff[2], bOff[2];
#pragma unroll
    for (int mi = 0; mi < 2; mi++) {
        int row = wm * 32 + mi * 16 + (lane & 15);
        int u   = lane >> 4;
        aOff[mi] = swz((uint32_t)(row * 128 + u * 16));
    }
#pragma unroll
    for (int p = 0; p < 2; p++) {
        int row = wn * 32 + p * 16 + ((lane >> 4) & 1) * 8 + (lane & 7);
        int u   = (lane >> 3) & 1;
        bOff[p] = swz((uint32_t)(row * 128 + u * 16));
    }

    float acc[2][4][4];
#pragma unroll
    for (int mi = 0; mi < 2; mi++)
#pragma unroll
        for (int ni = 0; ni < 4; ni++)
#pragma unroll
            for (int q = 0; q < 4; q++) acc[mi][ni][q] = 0.0f;

    // prologue: fully stage chunks 0 and 1
#pragma unroll
    for (int pc = 0; pc < 2; pc++) {
        float4 xa = *reinterpret_cast<const float4*>(ctx.xthr + pc * 16);
        float4 xb = *reinterpret_cast<const float4*>(ctx.xthr + pc * 16 + 4);
        float xs[8] = {xa.x, xa.y, xa.z, xa.w, xb.x, xb.y, xb.z, xb.w};
#pragma unroll
        for (int sl = 0; sl < 8; sl++) {
            if (sl < 4) produce_B_slice(ctx, pc, bBuf[pc], sl);
            produce_A_slice(ctx, aBuf[pc], xs[sl], sl);
        }
        CP_COMMIT();
    }

    int s_cons = 0, s_prod = 2;

    for (int c = 0; c < NCH; c++) {
        CP_WAIT1();
        __syncthreads();

        bool doprod = (c + 2 < NCH);
        float xs[8];
        if (doprod) {
            float4 xa = *reinterpret_cast<const float4*>(ctx.xthr + (c + 2) * 16);
            float4 xb = *reinterpret_cast<const float4*>(ctx.xthr + (c + 2) * 16 + 4);
            xs[0] = xa.x; xs[1] = xa.y; xs[2] = xa.z; xs[3] = xa.w;
            xs[4] = xb.x; xs[5] = xb.y; xs[6] = xb.z; xs[7] = xb.w;
        }

        uint32_t aB = aBuf[s_cons], bB = bBuf[s_cons];
        uint32_t aP = aBuf[s_prod], bP = bBuf[s_prod];

#pragma unroll
        for (int ks = 0; ks < 8; ks++) {
            int pl = ks >> 2;               // k-plane
            int kk = ks & 3;
            uint32_t aPl = aB + pl * A_PLANE;
            uint32_t bPl = bB + pl * B_PLANE;

            uint32_t a[2][4];
#pragma unroll
            for (int mi = 0; mi < 2; mi++)
                ldmx4(a[mi], aPl + (aOff[mi] ^ (kk * 32)));
            uint32_t b[4][2];
#pragma unroll
            for (int p = 0; p < 2; p++) {
                uint32_t r[4];
                ldmx4(r, bPl + (bOff[p] ^ (kk * 32)));
                b[2 * p][0] = r[0]; b[2 * p][1] = r[1];
                b[2 * p + 1][0] = r[2]; b[2 * p + 1][1] = r[3];
            }

            // production slice for chunk c+2, issued into the tensor-pipe shadow
            if (doprod) {
                if (ks < 4) produce_B_slice(ctx, c + 2, bP, ks);
                produce_A_slice(ctx, aP, xs[ks], ks);
            }

#pragma unroll
            for (int ni = 0; ni < 4; ni++)
#pragma unroll
                for (int mi = 0; mi < 2; mi++)
                    mma16816(acc[mi][ni], a[mi], b[ni]);
        }

        if (doprod) CP_COMMIT();

        if (++s_cons == STAGES) s_cons = 0;
        if (++s_prod == STAGES) s_prod = 0;
    }

    // epilogue: direct f32 stores from accumulators
    float* obase = out + (size_t)(Mtile * MT + wm * 32) * OUTF + Ntile * NT + wn * 32;
#pragma unroll
    for (int mi = 0; mi < 2; mi++) {
        int r0 = mi * 16 + (lane >> 2);
#pragma unroll
        for (int ni = 0; ni < 4; ni++) {
            int cl = ni * 8 + (lane & 3) * 2;
            float2 v0 = make_float2(acc[mi][ni][0], acc[mi][ni][1]);
            float2 v1 = make_float2(acc[mi][ni][2], acc[mi][ni][3]);
            *reinterpret_cast<float2*>(obase + (size_t)r0 * OUTF + cl) = v0;
            *reinterpret_cast<float2*>(obase + (size_t)(r0 + 8) * OUTF + cl) = v1;
        }
    }
}

// ---------------- launch ----------------
extern "C" void kernel_launch(void* const* d_in, const int* in_sizes, int n_in,
                              void* d_out, int out_size) {
    const float* x    = (const float*)d_in[0];
    const float* grid = (const float*)d_in[1];
    const float* W    = (const float*)d_in[2];
    float* out = (float*)d_out;

    cudaFuncSetAttribute(gk_kernel, cudaFuncAttributeMaxDynamicSharedMemorySize, SMEM_DYN);

    dim3 tb(32, 8);
    wt_kernel<<<dim3(KTOT / 32, OUTF / 32), tb>>>(W);
    gk_kernel<<<(BATCH / MT) * (OUTF / NT), THREADS, SMEM_DYN>>>(x, grid, out);
}

// round 10
// speedup vs baseline: 1.3107x; 1.3107x over previous
#include <cuda_runtime.h>
#include <cuda_fp16.h>
#include <cstdint>

#define DI __device__ __forceinline__

// ---------------- problem constants ----------------
constexpr int BATCH   = 16384;
constexpr int INF     = 512;
constexpr int OUTF    = 512;
constexpr int NG      = 8;
constexpr int KTOT    = INF * NG;    // 4096
constexpr int KC      = 64;          // K per chunk (128B fp16 row)
constexpr int NCH     = KTOT / KC;   // 64 chunks
constexpr int MT      = 64;          // M tile per CTA
constexpr int NT      = 128;         // N tile per CTA
constexpr int THREADS = 128;         // 4 warps
constexpr int STAGES  = 2;

constexpr int A_BYTES     = 64 * 128;             // 8 KB
constexpr int B_BYTES     = 128 * 128;            // 16 KB
constexpr int STAGE_BYTES = A_BYTES + B_BYTES;    // 24 KB
constexpr int SMEM_DYN    = STAGES * STAGE_BYTES + 1024;   // ~49 KB -> 4 CTAs/SM

// fp16 W transposed to [OUTF, KTOT], K contiguous
__device__ __half g_Wt[(size_t)OUTF * KTOT];

// ---------------- PTX helpers ----------------
DI uint32_t smem_u32(const void* p) {
    uint32_t a;
    asm("{ .reg .u64 t; cvta.to.shared.u64 t, %1; cvt.u32.u64 %0, t; }" : "=r"(a) : "l"(p));
    return a;
}

// pack (lo,hi) fp32 -> f16x2 and take 2^x on both halves in one MUFU op
DI uint32_t ex2_f16x2(float lo, float hi) {
    uint32_t d;
    asm("{ .reg .b32 t; cvt.rn.f16x2.f32 t, %1, %2; ex2.approx.f16x2 %0, t; }"
        : "=r"(d) : "f"(hi), "f"(lo));
    return d;
}

DI uint32_t swz(uint32_t off) { return off ^ ((off >> 3) & 0x70u); }

DI void ldmx4(uint32_t* r, uint32_t addr) {
    asm volatile("ldmatrix.sync.aligned.m8n8.x4.shared.b16 {%0,%1,%2,%3}, [%4];"
                 : "=r"(r[0]), "=r"(r[1]), "=r"(r[2]), "=r"(r[3]) : "r"(addr));
}

DI void mma16816(float* c, const uint32_t* a, const uint32_t* b) {
    asm volatile(
        "mma.sync.aligned.m16n8k16.row.col.f32.f16.f16.f32 "
        "{%0,%1,%2,%3}, {%4,%5,%6,%7}, {%8,%9}, {%0,%1,%2,%3};"
        : "+f"(c[0]), "+f"(c[1]), "+f"(c[2]), "+f"(c[3])
        : "r"(a[0]), "r"(a[1]), "r"(a[2]), "r"(a[3]), "r"(b[0]), "r"(b[1]));
}

DI void cp_async16(uint32_t dst, const void* src) {
    asm volatile("cp.async.cg.shared.global [%0], [%1], 16;" :: "r"(dst), "l"(src) : "memory");
}
#define CP_COMMIT() asm volatile("cp.async.commit_group;" ::: "memory")
#define CP_WAIT0()  asm volatile("cp.async.wait_group 0;" ::: "memory")

// ---------------- kernel 1: W[K,N] f32 -> Wt[N,K] fp16 ----------------
__global__ void wt_kernel(const float* __restrict__ W) {
    __shared__ float tile[32][33];
    int k0 = blockIdx.x * 32, n0 = blockIdx.y * 32;
    int tx = threadIdx.x, ty = threadIdx.y;
#pragma unroll
    for (int i = 0; i < 32; i += 8)
        tile[ty + i][tx] = W[(size_t)(k0 + ty + i) * OUTF + n0 + tx];
    __syncthreads();
#pragma unroll
    for (int i = 0; i < 32; i += 8)
        g_Wt[(size_t)(n0 + ty + i) * KTOT + k0 + tx] = __float2half_rn(tile[tx][ty + i]);
}

// ---------------- kernel 2: fused basis + mma.sync GEMM ----------------
struct Ctx {
    float aco;
    float nb[8];
    const float* xthr;      // x row m, feature offset half*4
    const __half* wbase;    // Wt + Ntile*NT*KTOT
    int tid, m, half;
};

// B tile: 16 KB = 8 cp.async per thread (issued together at chunk top)
DI void produce_B(const Ctx& ctx, int c, uint32_t bBase) {
#pragma unroll
    for (int i = 0; i < 8; i++) {
        int idx = ctx.tid + THREADS * i;  // 0..1023 16B units
        int n   = idx >> 3;               // local out-feature row (0..127)
        int seg = idx & 7;                // 16B segment within 128B row
        uint32_t off = (uint32_t)(n * 128 + seg * 16);
        const void* g = (const void*)(ctx.wbase + (size_t)n * KTOT + c * KC + seg * 8);
        cp_async16(bBase + swz(off), g);
    }
}

// A slice: one feature (sl = 0..3) -> 8 gaussian values -> one 16B store
DI void produce_A_slice(const Ctx& ctx, uint32_t aBase, float xf, int sl) {
    uint32_t pk[4];
#pragma unroll
    for (int q = 0; q < 4; q++) {
        float v0 = fmaf(xf, ctx.aco, ctx.nb[2 * q]);
        float v1 = fmaf(xf, ctx.aco, ctx.nb[2 * q + 1]);
        // exp(-u^2) = 2^(-(u*sqrt(log2 e))^2); both halves in one MUFU
        pk[q] = ex2_f16x2(-(v0 * v0), -(v1 * v1));
    }
    uint32_t off = (uint32_t)(ctx.m * 128 + (ctx.half * 4 + sl) * 16);
    asm volatile("st.shared.v4.b32 [%0], {%1, %2, %3, %4};"
                 :: "r"(aBase + swz(off)), "r"(pk[0]), "r"(pk[1]), "r"(pk[2]), "r"(pk[3])
                 : "memory");
}

__global__ void __launch_bounds__(THREADS, 4)
gk_kernel(const float* __restrict__ x, const float* __restrict__ grid,
          float* __restrict__ out)
{
    extern __shared__ char smem[];
    uint32_t sb = (smem_u32(smem) + 1023u) & ~1023u;

    int tid  = threadIdx.x;
    int lane = tid & 31;
    int wid  = tid >> 5;
    // m-major CTA order: consecutive bids share the same 1MB B slab (L2 reuse)
    int Mtile = blockIdx.x & 255;
    int Ntile = blockIdx.x >> 8;

    Ctx ctx;
    ctx.aco = 1.75f * 1.2011224087864498f;   // (1/h)*sqrt(log2 e), h = 4/7
#pragma unroll
    for (int g = 0; g < 8; g++) ctx.nb[g] = -grid[g] * ctx.aco;
    ctx.tid   = tid;
    ctx.m     = tid >> 1;                    // 0..63
    ctx.half  = tid & 1;
    ctx.xthr  = x + (size_t)(Mtile * MT + ctx.m) * INF + ctx.half * 4;
    ctx.wbase = g_Wt + (size_t)(Ntile * NT) * KTOT;

    uint32_t aBuf[STAGES], bBuf[STAGES];
#pragma unroll
    for (int s = 0; s < STAGES; s++) {
        aBuf[s] = sb + s * STAGE_BYTES;
        bBuf[s] = aBuf[s] + A_BYTES;
    }

    // warp tiling: 4 warps = 1(M) x 4(N); warp tile 64x32
    int wn = wid;

    uint32_t aOff[4], bOff[2];
#pragma unroll
    for (int mi = 0; mi < 4; mi++) {
        int row = mi * 16 + (lane & 15);
        int u   = lane >> 4;
        aOff[mi] = swz((uint32_t)(row * 128 + u * 16));
    }
#pragma unroll
    for (int p = 0; p < 2; p++) {
        int row = wn * 32 + p * 16 + ((lane >> 4) & 1) * 8 + (lane & 7);
        int u   = (lane >> 3) & 1;
        bOff[p] = swz((uint32_t)(row * 128 + u * 16));
    }

    float acc[4][4][4];
#pragma unroll
    for (int mi = 0; mi < 4; mi++)
#pragma unroll
        for (int ni = 0; ni < 4; ni++)
#pragma unroll
            for (int q = 0; q < 4; q++) acc[mi][ni][q] = 0.0f;

    // prologue: stage chunk 0
    {
        float4 x0 = *reinterpret_cast<const float4*>(ctx.xthr);
        produce_B(ctx, 0, bBuf[0]);
        float xs[4] = {x0.x, x0.y, x0.z, x0.w};
#pragma unroll
        for (int sl = 0; sl < 4; sl++) produce_A_slice(ctx, aBuf[0], xs[sl], sl);
        CP_COMMIT();
    }

    for (int c = 0; c < NCH; c++) {
        CP_WAIT0();
        __syncthreads();

        int cur = c & 1;
        bool doprod = (c + 1 < NCH);
        float xs[4];
        if (doprod) {
            // issue all B cp.asyncs for c+1 up front: full chunk of latency slack
            produce_B(ctx, c + 1, bBuf[cur ^ 1]);
            CP_COMMIT();
            float4 xn = *reinterpret_cast<const float4*>(ctx.xthr + (c + 1) * NG);
            xs[0] = xn.x; xs[1] = xn.y; xs[2] = xn.z; xs[3] = xn.w;
        }

        uint32_t aB = aBuf[cur], bB = bBuf[cur];
        uint32_t aP = aBuf[cur ^ 1];

#pragma unroll
        for (int ks = 0; ks < 4; ks++) {
            uint32_t a[4][4];
#pragma unroll
            for (int mi = 0; mi < 4; mi++)
                ldmx4(a[mi], aB + (aOff[mi] ^ (ks * 32)));
            uint32_t b[4][2];
#pragma unroll
            for (int p = 0; p < 2; p++) {
                uint32_t r[4];
                ldmx4(r, bB + (bOff[p] ^ (ks * 32)));
                b[2 * p][0] = r[0]; b[2 * p][1] = r[1];
                b[2 * p + 1][0] = r[2]; b[2 * p + 1][1] = r[3];
            }

            // one A slice of chunk c+1 into the tensor-pipe shadow
            if (doprod) produce_A_slice(ctx, aP, xs[ks], ks);

#pragma unroll
            for (int ni = 0; ni < 4; ni++)
#pragma unroll
                for (int mi = 0; mi < 4; mi++)
                    mma16816(acc[mi][ni], a[mi], b[ni]);
        }
    }

    // epilogue: direct f32 stores from accumulators
    float* obase = out + (size_t)(Mtile * MT) * OUTF + Ntile * NT + wn * 32;
#pragma unroll
    for (int mi = 0; mi < 4; mi++) {
        int r0 = mi * 16 + (lane >> 2);
#pragma unroll
        for (int ni = 0; ni < 4; ni++) {
            int cl = ni * 8 + (lane & 3) * 2;
            float2 v0 = make_float2(acc[mi][ni][0], acc[mi][ni][1]);
            float2 v1 = make_float2(acc[mi][ni][2], acc[mi][ni][3]);
            *reinterpret_cast<float2*>(obase + (size_t)r0 * OUTF + cl) = v0;
            *reinterpret_cast<float2*>(obase + (size_t)(r0 + 8) * OUTF + cl) = v1;
        }
    }
}

// ---------------- launch ----------------
extern "C" void kernel_launch(void* const* d_in, const int* in_sizes, int n_in,
                              void* d_out, int out_size) {
    const float* x    = (const float*)d_in[0];
    const float* grid = (const float*)d_in[1];
    const float* W    = (const float*)d_in[2];
    float* out = (float*)d_out;

    cudaFuncSetAttribute(gk_kernel, cudaFuncAttributeMaxDynamicSharedMemorySize, SMEM_DYN);

    dim3 tb(32, 8);
    wt_kernel<<<dim3(KTOT / 32, OUTF / 32), tb>>>(W);
    gk_kernel<<<(BATCH / MT) * (OUTF / NT), THREADS, SMEM_DYN>>>(x, grid, out);
}

// round 12
// speedup vs baseline: 1.3767x; 1.0504x over previous
#include <cuda_runtime.h>
#include <cuda_fp16.h>
#include <cstdint>

#define DI __device__ __forceinline__

// ---------------- problem constants ----------------
constexpr int BATCH   = 16384;
constexpr int INF     = 512;
constexpr int OUTF    = 512;
constexpr int NG      = 8;
constexpr int KTOT    = INF * NG;    // 4096
constexpr int KC      = 64;          // K per chunk (128B fp16 row)
constexpr int NCH     = KTOT / KC;   // 64 chunks
constexpr int MT      = 64;          // M tile per CTA
constexpr int NT      = 128;         // N tile per CTA
constexpr int THREADS = 128;         // 4 warps
constexpr int STAGES  = 2;

constexpr int A_BYTES     = 64 * 128;             // 8 KB
constexpr int B_BYTES     = 128 * 128;            // 16 KB
constexpr int STAGE_BYTES = A_BYTES + B_BYTES;    // 24 KB
constexpr int SMEM_DYN    = STAGES * STAGE_BYTES + 1024;   // ~49 KB -> 4 CTAs/SM

// fp16 W transposed to [OUTF, KTOT], K contiguous
__device__ __half g_Wt[(size_t)OUTF * KTOT];

// ---------------- PTX helpers ----------------
DI uint32_t smem_u32(const void* p) {
    uint32_t a;
    asm("{ .reg .u64 t; cvta.to.shared.u64 t, %1; cvt.u32.u64 %0, t; }" : "=r"(a) : "l"(p));
    return a;
}

// pack (lo,hi) fp32 -> f16x2 and take 2^x on both halves in one MUFU op
DI uint32_t ex2_f16x2(float lo, float hi) {
    uint32_t d;
    asm("{ .reg .b32 t; cvt.rn.f16x2.f32 t, %1, %2; ex2.approx.f16x2 %0, t; }"
        : "=r"(d) : "f"(hi), "f"(lo));
    return d;
}

DI uint32_t swz(uint32_t off) { return off ^ ((off >> 3) & 0x70u); }

DI void ldmx4(uint32_t* r, uint32_t addr) {
    asm volatile("ldmatrix.sync.aligned.m8n8.x4.shared.b16 {%0,%1,%2,%3}, [%4];"
                 : "=r"(r[0]), "=r"(r[1]), "=r"(r[2]), "=r"(r[3]) : "r"(addr));
}

DI void mma16816(float* c, const uint32_t* a, const uint32_t* b) {
    asm volatile(
        "mma.sync.aligned.m16n8k16.row.col.f32.f16.f16.f32 "
        "{%0,%1,%2,%3}, {%4,%5,%6,%7}, {%8,%9}, {%0,%1,%2,%3};"
        : "+f"(c[0]), "+f"(c[1]), "+f"(c[2]), "+f"(c[3])
        : "r"(a[0]), "r"(a[1]), "r"(a[2]), "r"(a[3]), "r"(b[0]), "r"(b[1]));
}

DI void cp_async16(uint32_t dst, const void* src) {
    asm volatile("cp.async.cg.shared.global [%0], [%1], 16;" :: "r"(dst), "l"(src) : "memory");
}
#define CP_COMMIT() asm volatile("cp.async.commit_group;" ::: "memory")
#define CP_WAIT0()  asm volatile("cp.async.wait_group 0;" ::: "memory")

// ---------------- kernel 1: W[K,N] f32 -> Wt[N,K] fp16 ----------------
__global__ void wt_kernel(const float* __restrict__ W) {
    __shared__ float tile[32][33];
    int k0 = blockIdx.x * 32, n0 = blockIdx.y * 32;
    int tx = threadIdx.x, ty = threadIdx.y;
#pragma unroll
    for (int i = 0; i < 32; i += 8)
        tile[ty + i][tx] = W[(size_t)(k0 + ty + i) * OUTF + n0 + tx];
    __syncthreads();
#pragma unroll
    for (int i = 0; i < 32; i += 8)
        g_Wt[(size_t)(n0 + ty + i) * KTOT + k0 + tx] = __float2half_rn(tile[tx][ty + i]);
}

// ---------------- kernel 2: fused basis + mma.sync GEMM ----------------

// B tile: 8 cp.async per thread; dst/src are affine in slice index i
// dst_i = bDst + i*2048 (swizzle mask invariant: i moves n in steps of 16,
// so (off>>3)&0x70 is unchanged; i*2048 occupies bits >= 11)
// src_i = bSrc + i*16*KTOT halves
DI void produce_B(uint32_t bDst, const __half* bSrc) {
#pragma unroll
    for (int i = 0; i < 8; i++)
        cp_async16(bDst + i * 2048, (const void*)(bSrc + (size_t)i * 16 * KTOT));
}

// A slice: one feature -> 8 gaussian values -> one 16B store at exact addr
DI void produce_A_slice(uint32_t aDst, const float* nb, float aco, float xf) {
    uint32_t pk[4];
#pragma unroll
    for (int q = 0; q < 4; q++) {
        float v0 = fmaf(xf, aco, nb[2 * q]);
        float v1 = fmaf(xf, aco, nb[2 * q + 1]);
        // exp(-u^2) = 2^(-(u*sqrt(log2 e))^2); both halves in one MUFU
        pk[q] = ex2_f16x2(-(v0 * v0), -(v1 * v1));
    }
    asm volatile("st.shared.v4.b32 [%0], {%1, %2, %3, %4};"
                 :: "r"(aDst), "r"(pk[0]), "r"(pk[1]), "r"(pk[2]), "r"(pk[3])
                 : "memory");
}

__global__ void __launch_bounds__(THREADS, 4)
gk_kernel(const float* __restrict__ x, const float* __restrict__ grid,
          float* __restrict__ out)
{
    extern __shared__ char smem[];
    uint32_t sb = (smem_u32(smem) + 1023u) & ~1023u;

    int tid  = threadIdx.x;
    int lane = tid & 31;
    int wid  = tid >> 5;
    // m-major CTA order: consecutive bids share the same 1MB B slab (L2 reuse)
    int Mtile = blockIdx.x & 255;
    int Ntile = blockIdx.x >> 8;

    float aco = 1.75f * 1.2011224087864498f;   // (1/h)*sqrt(log2 e), h = 4/7
    float nb[8];
#pragma unroll
    for (int g = 0; g < 8; g++) nb[g] = -grid[g] * aco;

    uint32_t aBuf[STAGES], bBuf[STAGES];
#pragma unroll
    for (int s = 0; s < STAGES; s++) {
        aBuf[s] = sb + s * STAGE_BYTES;
        bBuf[s] = aBuf[s] + A_BYTES;
    }

    // ---- hoisted producer state ----
    // B: thread covers 16B unit (n0 = tid/8, seg = tid%8) of each 2KB slice
    int n0  = tid >> 3, seg = tid & 7;
    uint32_t bD0 = swz((uint32_t)(n0 * 128 + seg * 16));   // slice-invariant swizzle
    const __half* bSrcNext = g_Wt + (size_t)(Ntile * NT + n0) * KTOT + seg * 8;
    // A: thread covers row m = tid/2, features half*4 .. half*4+3 of each chunk.
    // sl*16 overlaps the swizzle mask bits, so precompute all 4 swizzled offsets.
    int m = tid >> 1, half = tid & 1;
    uint32_t aDsw[4];
#pragma unroll
    for (int sl = 0; sl < 4; sl++)
        aDsw[sl] = swz((uint32_t)(m * 128 + (half * 4 + sl) * 16));
    const float* xNext = x + (size_t)(Mtile * MT + m) * INF + half * 4;

    // warp tiling: 4 warps = 1(M) x 4(N); warp tile 64x32
    int wn = wid;

    uint32_t aOff[4], bOff[2];
#pragma unroll
    for (int mi = 0; mi < 4; mi++) {
        int row = mi * 16 + (lane & 15);
        int u   = lane >> 4;
        aOff[mi] = swz((uint32_t)(row * 128 + u * 16));
    }
#pragma unroll
    for (int p = 0; p < 2; p++) {
        int row = wn * 32 + p * 16 + ((lane >> 4) & 1) * 8 + (lane & 7);
        int u   = (lane >> 3) & 1;
        bOff[p] = swz((uint32_t)(row * 128 + u * 16));
    }

    float acc[4][4][4];
#pragma unroll
    for (int mi = 0; mi < 4; mi++)
#pragma unroll
        for (int ni = 0; ni < 4; ni++)
#pragma unroll
            for (int q = 0; q < 4; q++) acc[mi][ni][q] = 0.0f;

    // prologue: stage chunk 0
    {
        produce_B(bBuf[0] + bD0, bSrcNext);
        bSrcNext += KC;
        float4 x0 = *reinterpret_cast<const float4*>(xNext);
        xNext += NG;
        float xs[4] = {x0.x, x0.y, x0.z, x0.w};
#pragma unroll
        for (int sl = 0; sl < 4; sl++)
            produce_A_slice(aBuf[0] + aDsw[sl], nb, aco, xs[sl]);
        CP_COMMIT();
    }

    for (int c = 0; c < NCH; c++) {
        CP_WAIT0();
        __syncthreads();

        int cur = c & 1;
        bool doprod = (c + 1 < NCH);
        float xs[4];
        if (doprod) {
            // all B cp.asyncs for c+1 up front: full chunk of latency slack
            produce_B(bBuf[cur ^ 1] + bD0, bSrcNext);
            bSrcNext += KC;
            CP_COMMIT();
            float4 xn = *reinterpret_cast<const float4*>(xNext);
            xNext += NG;
            xs[0] = xn.x; xs[1] = xn.y; xs[2] = xn.z; xs[3] = xn.w;
        }

        uint32_t aB = aBuf[cur], bB = bBuf[cur];
        uint32_t aP = aBuf[cur ^ 1];

#pragma unroll
        for (int ks = 0; ks < 4; ks++) {
            uint32_t a[4][4];
#pragma unroll
            for (int mi = 0; mi < 4; mi++)
                ldmx4(a[mi], aB + (aOff[mi] ^ (ks * 32)));
            uint32_t b[4][2];
#pragma unroll
            for (int p = 0; p < 2; p++) {
                uint32_t r[4];
                ldmx4(r, bB + (bOff[p] ^ (ks * 32)));
                b[2 * p][0] = r[0]; b[2 * p][1] = r[1];
                b[2 * p + 1][0] = r[2]; b[2 * p + 1][1] = r[3];
            }

            // one A slice of chunk c+1 into the tensor-pipe shadow
            if (doprod) produce_A_slice(aP + aDsw[ks], nb, aco, xs[ks]);

#pragma unroll
            for (int ni = 0; ni < 4; ni++)
#pragma unroll
                for (int mi = 0; mi < 4; mi++)
                    mma16816(acc[mi][ni], a[mi], b[ni]);
        }
    }

    // epilogue: direct f32 stores from accumulators
    float* obase = out + (size_t)(Mtile * MT) * OUTF + Ntile * NT + wn * 32;
#pragma unroll
    for (int mi = 0; mi < 4; mi++) {
        int r0 = mi * 16 + (lane >> 2);
#pragma unroll
        for (int ni = 0; ni < 4; ni++) {
            int cl = ni * 8 + (lane & 3) * 2;
            float2 v0 = make_float2(acc[mi][ni][0], acc[mi][ni][1]);
            float2 v1 = make_float2(acc[mi][ni][2], acc[mi][ni][3]);
            *reinterpret_cast<float2*>(obase + (size_t)r0 * OUTF + cl) = v0;
            *reinterpret_cast<float2*>(obase + (size_t)(r0 + 8) * OUTF + cl) = v1;
        }
    }
}

// ---------------- launch ----------------
extern "C" void kernel_launch(void* const* d_in, const int* in_sizes, int n_in,
                              void* d_out, int out_size) {
    const float* x    = (const float*)d_in[0];
    const float* grid = (const float*)d_in[1];
    const float* W    = (const float*)d_in[2];
    float* out = (float*)d_out;

    cudaFuncSetAttribute(gk_kernel, cudaFuncAttributeMaxDynamicSharedMemorySize, SMEM_DYN);

    dim3 tb(32, 8);
    wt_kernel<<<dim3(KTOT / 32, OUTF / 32), tb>>>(W);
    gk_kernel<<<(BATCH / MT) * (OUTF / NT), THREADS, SMEM_DYN>>>(x, grid, out);
}

// round 13
// speedup vs baseline: 1.4478x; 1.0517x over previous
#include <cuda_runtime.h>
#include <cuda_fp16.h>
#include <cstdint>

#define DI __device__ __forceinline__

// ---------------- problem constants ----------------
constexpr int BATCH   = 16384;
constexpr int INF     = 512;
constexpr int OUTF    = 512;
constexpr int NG      = 8;
constexpr int KTOT    = INF * NG;    // 4096
constexpr int KC      = 64;          // K per chunk (128B fp16 row)
constexpr int NCH     = KTOT / KC;   // 64 chunks
constexpr int MT      = 64;          // M tile per CTA
constexpr int NT      = 128;         // N tile per CTA
constexpr int THREADS = 128;         // 4 warps
constexpr int STAGES  = 2;

constexpr int A_BYTES     = 64 * 128;             // 8 KB
constexpr int B_BYTES     = 128 * 128;            // 16 KB
constexpr int STAGE_BYTES = A_BYTES + B_BYTES;    // 24 KB
constexpr int SMEM_DYN    = STAGES * STAGE_BYTES + 1024;   // ~49 KB -> 4 CTAs/SM

// fp16 W transposed to [OUTF, KTOT], K contiguous
__device__ __half g_Wt[(size_t)OUTF * KTOT];

// ---------------- PTX helpers ----------------
DI uint32_t smem_u32(const void* p) {
    uint32_t a;
    asm("{ .reg .u64 t; cvta.to.shared.u64 t, %1; cvt.u32.u64 %0, t; }" : "=r"(a) : "l"(p));
    return a;
}

// pack (lo,hi) fp32 -> f16x2 and take 2^x on both halves in one MUFU op
DI uint32_t ex2_f16x2(float lo, float hi) {
    uint32_t d;
    asm("{ .reg .b32 t; cvt.rn.f16x2.f32 t, %1, %2; ex2.approx.f16x2 %0, t; }"
        : "=r"(d) : "f"(hi), "f"(lo));
    return d;
}

DI uint32_t swz(uint32_t off) { return off ^ ((off >> 3) & 0x70u); }

DI void ldmx4(uint32_t* r, uint32_t addr) {
    asm volatile("ldmatrix.sync.aligned.m8n8.x4.shared.b16 {%0,%1,%2,%3}, [%4];"
                 : "=r"(r[0]), "=r"(r[1]), "=r"(r[2]), "=r"(r[3]) : "r"(addr));
}

DI void mma16816(float* c, const uint32_t* a, const uint32_t* b) {
    asm volatile(
        "mma.sync.aligned.m16n8k16.row.col.f32.f16.f16.f32 "
        "{%0,%1,%2,%3}, {%4,%5,%6,%7}, {%8,%9}, {%0,%1,%2,%3};"
        : "+f"(c[0]), "+f"(c[1]), "+f"(c[2]), "+f"(c[3])
        : "r"(a[0]), "r"(a[1]), "r"(a[2]), "r"(a[3]), "r"(b[0]), "r"(b[1]));
}

DI void cp_async16(uint32_t dst, const void* src) {
    asm volatile("cp.async.cg.shared.global [%0], [%1], 16;" :: "r"(dst), "l"(src) : "memory");
}
#define CP_COMMIT() asm volatile("cp.async.commit_group;" ::: "memory")
#define CP_WAIT0()  asm volatile("cp.async.wait_group 0;" ::: "memory")

// ---------------- kernel 1: W[K,N] f32 -> Wt[N,K] fp16 ----------------
__global__ void wt_kernel(const float* __restrict__ W) {
    __shared__ float tile[32][33];
    int k0 = blockIdx.x * 32, n0 = blockIdx.y * 32;
    int tx = threadIdx.x, ty = threadIdx.y;
#pragma unroll
    for (int i = 0; i < 32; i += 8)
        tile[ty + i][tx] = W[(size_t)(k0 + ty + i) * OUTF + n0 + tx];
    __syncthreads();
#pragma unroll
    for (int i = 0; i < 32; i += 8)
        g_Wt[(size_t)(n0 + ty + i) * KTOT + k0 + tx] = __float2half_rn(tile[tx][ty + i]);
}

// ---------------- kernel 2: fused basis + mma.sync GEMM ----------------

// B tile: 8 cp.async per thread; dst/src affine in slice index i
DI void produce_B(uint32_t bDst, const __half* bSrc) {
#pragma unroll
    for (int i = 0; i < 8; i++)
        cp_async16(bDst + i * 2048, (const void*)(bSrc + (size_t)i * 16 * KTOT));
}

// A slice: one feature -> 8 gaussian values -> one 16B store
DI void produce_A_slice(uint32_t aDst, const float* nb, float aco, float xf) {
    uint32_t pk[4];
#pragma unroll
    for (int q = 0; q < 4; q++) {
        float v0 = fmaf(xf, aco, nb[2 * q]);
        float v1 = fmaf(xf, aco, nb[2 * q + 1]);
        // exp(-u^2) = 2^(-(u*sqrt(log2 e))^2); both halves in one MUFU
        pk[q] = ex2_f16x2(-(v0 * v0), -(v1 * v1));
    }
    asm volatile("st.shared.v4.b32 [%0], {%1, %2, %3, %4};"
                 :: "r"(aDst), "r"(pk[0]), "r"(pk[1]), "r"(pk[2]), "r"(pk[3])
                 : "memory");
}

__global__ void __launch_bounds__(THREADS, 4)
gk_kernel(const float* __restrict__ x, const float* __restrict__ grid,
          float* __restrict__ out)
{
    extern __shared__ char smem[];
    uint32_t sb = (smem_u32(smem) + 1023u) & ~1023u;

    int tid  = threadIdx.x;
    int lane = tid & 31;
    int wid  = tid >> 5;
    // m-major CTA order: consecutive bids share the same 1MB B slab (L2 reuse)
    int Mtile = blockIdx.x & 255;
    int Ntile = blockIdx.x >> 8;

    float aco = 1.75f * 1.2011224087864498f;   // (1/h)*sqrt(log2 e), h = 4/7
    float nb[8];
#pragma unroll
    for (int g = 0; g < 8; g++) nb[g] = -grid[g] * aco;

    uint32_t aBuf[STAGES], bBuf[STAGES];
#pragma unroll
    for (int s = 0; s < STAGES; s++) {
        aBuf[s] = sb + s * STAGE_BYTES;
        bBuf[s] = aBuf[s] + A_BYTES;
    }

    // ---- hoisted producer state ----
    int n0  = tid >> 3, seg = tid & 7;
    uint32_t bD0 = swz((uint32_t)(n0 * 128 + seg * 16));   // slice-invariant swizzle
    const __half* bSrcNext = g_Wt + (size_t)(Ntile * NT + n0) * KTOT + seg * 8;
    int m = tid >> 1, half = tid & 1;
    uint32_t aDsw[4];
#pragma unroll
    for (int sl = 0; sl < 4; sl++)
        aDsw[sl] = swz((uint32_t)(m * 128 + (half * 4 + sl) * 16));
    const float* xNext = x + (size_t)(Mtile * MT + m) * INF + half * 4;

    // warp tiling: 4 warps = 1(M) x 4(N); warp tile 64x32
    int wn = wid;

    uint32_t aOff[4], bOff[2];
#pragma unroll
    for (int mi = 0; mi < 4; mi++) {
        int row = mi * 16 + (lane & 15);
        int u   = lane >> 4;
        aOff[mi] = swz((uint32_t)(row * 128 + u * 16));
    }
#pragma unroll
    for (int p = 0; p < 2; p++) {
        int row = wn * 32 + p * 16 + ((lane >> 4) & 1) * 8 + (lane & 7);
        int u   = (lane >> 3) & 1;
        bOff[p] = swz((uint32_t)(row * 128 + u * 16));
    }

    float acc[4][4][4];
#pragma unroll
    for (int mi = 0; mi < 4; mi++)
#pragma unroll
        for (int ni = 0; ni < 4; ni++)
#pragma unroll
            for (int q = 0; q < 4; q++) acc[mi][ni][q] = 0.0f;

    // prologue: stage chunk 0; prefetch x for chunk 1
    float xsN[4];
    {
        produce_B(bBuf[0] + bD0, bSrcNext);
        bSrcNext += KC;
        float4 x0 = *reinterpret_cast<const float4*>(xNext);
        xNext += NG;
        float xs0[4] = {x0.x, x0.y, x0.z, x0.w};
#pragma unroll
        for (int sl = 0; sl < 4; sl++)
            produce_A_slice(aBuf[0] + aDsw[sl], nb, aco, xs0[sl]);
        CP_COMMIT();
        float4 x1 = *reinterpret_cast<const float4*>(xNext);   // chunk 1 x, prefetched
        xNext += NG;
        xsN[0] = x1.x; xsN[1] = x1.y; xsN[2] = x1.z; xsN[3] = x1.w;
    }

    for (int c = 0; c < NCH; c++) {
        CP_WAIT0();
        __syncthreads();

        int cur = c & 1;
        bool doprod = (c + 1 < NCH);
        if (doprod) {
            // B cp.asyncs for c+1: full chunk of latency slack
            produce_B(bBuf[cur ^ 1] + bD0, bSrcNext);
            bSrcNext += KC;
            CP_COMMIT();
            // A for c+1 from prefetched xsN (no LDG dependency here)
            uint32_t aP = aBuf[cur ^ 1];
#pragma unroll
            for (int sl = 0; sl < 4; sl++)
                produce_A_slice(aP + aDsw[sl], nb, aco, xsN[sl]);
        }
        // prefetch x for chunk c+2 (consumed next iteration)
        if (c + 2 < NCH) {
            float4 xn = *reinterpret_cast<const float4*>(xNext);
            xNext += NG;
            xsN[0] = xn.x; xsN[1] = xn.y; xsN[2] = xn.z; xsN[3] = xn.w;
        }

        uint32_t aB = aBuf[cur], bB = bBuf[cur];

        // software-pipelined fragment loop: load ks+1 before MMAs of ks
        uint32_t a[2][4][4], b[2][4][2];
#pragma unroll
        for (int mi = 0; mi < 4; mi++)
            ldmx4(a[0][mi], aB + aOff[mi]);
#pragma unroll
        for (int p = 0; p < 2; p++) {
            uint32_t r[4];
            ldmx4(r, bB + bOff[p]);
            b[0][2 * p][0] = r[0]; b[0][2 * p][1] = r[1];
            b[0][2 * p + 1][0] = r[2]; b[0][2 * p + 1][1] = r[3];
        }

#pragma unroll
        for (int ks = 0; ks < 4; ks++) {
            int cb = ks & 1, nxt = cb ^ 1;
            if (ks < 3) {
#pragma unroll
                for (int mi = 0; mi < 4; mi++)
                    ldmx4(a[nxt][mi], aB + (aOff[mi] ^ ((ks + 1) * 32)));
#pragma unroll
                for (int p = 0; p < 2; p++) {
                    uint32_t r[4];
                    ldmx4(r, bB + (bOff[p] ^ ((ks + 1) * 32)));
                    b[nxt][2 * p][0] = r[0]; b[nxt][2 * p][1] = r[1];
                    b[nxt][2 * p + 1][0] = r[2]; b[nxt][2 * p + 1][1] = r[3];
                }
            }
#pragma unroll
            for (int ni = 0; ni < 4; ni++)
#pragma unroll
                for (int mi = 0; mi < 4; mi++)
                    mma16816(acc[mi][ni], a[cb][mi], b[cb][ni]);
        }
    }

    // epilogue: direct f32 stores from accumulators
    float* obase = out + (size_t)(Mtile * MT) * OUTF + Ntile * NT + wn * 32;
#pragma unroll
    for (int mi = 0; mi < 4; mi++) {
        int r0 = mi * 16 + (lane >> 2);
#pragma unroll
        for (int ni = 0; ni < 4; ni++) {
            int cl = ni * 8 + (lane & 3) * 2;
            float2 v0 = make_float2(acc[mi][ni][0], acc[mi][ni][1]);
            float2 v1 = make_float2(acc[mi][ni][2], acc[mi][ni][3]);
            *reinterpret_cast<float2*>(obase + (size_t)r0 * OUTF + cl) = v0;
            *reinterpret_cast<float2*>(obase + (size_t)(r0 + 8) * OUTF + cl) = v1;
        }
    }
}

// ---------------- launch ----------------
extern "C" void kernel_launch(void* const* d_in, const int* in_sizes, int n_in,
                              void* d_out, int out_size) {
    const float* x    = (const float*)d_in[0];
    const float* grid = (const float*)d_in[1];
    const float* W    = (const float*)d_in[2];
    float* out = (float*)d_out;

    cudaFuncSetAttribute(gk_kernel, cudaFuncAttributeMaxDynamicSharedMemorySize, SMEM_DYN);

    dim3 tb(32, 8);
    wt_kernel<<<dim3(KTOT / 32, OUTF / 32), tb>>>(W);
    gk_kernel<<<(BATCH / MT) * (OUTF / NT), THREADS, SMEM_DYN>>>(x, grid, out);
}